// round 13
// baseline (speedup 1.0000x reference)
#include <cuda_runtime.h>
#include <cuda_fp16.h>
#include <math.h>
#include <stdint.h>

#define NN 100000
#define NE 1600000
#define DH 128
#define NPAD 100096                  // padded rows (multiple of 128)
#define NT64 1564                    // NPAD / 64 tiles
#define SCAN_B 1024
#define NB ((NN + SCAN_B - 1) / SCAN_B)
#define NCHG 16                      // gather progress chunks
#define CHB 782                      // gather blocks per chunk (12500 = 15*782 + 770)

// ---------------- device scratch (no allocations allowed) ----------------
__device__ int     g_is64;
__device__ int     g_deg[NN];
__device__ int     g_cur[NN];
__device__ int     g_scan[NB * SCAN_B];
__device__ int     g_bsum[NB];
__device__ int     g_boff[NB];
__device__ int     g_off[NN + 1];
__device__ int     g_csr[NE];                         // src ids grouped by dst
__device__ float   g_dinv[NN];
__device__ __half2 g_xsh[(size_t)NN * 64];            // dinv-scaled x fp16, 25.6MB
__device__ __align__(16) __half g_af[(size_t)NPAD * DH];   // agg fp16 (pad rows stay 0)
__device__ __align__(16) unsigned char g_bimg[65536];      // B fp16, [n][k] swizzled
__device__ volatile int g_flag[NCHG];                 // gather chunk-done flags
__device__ int     g_cnt[NCHG];                       // gather chunk block counters

// ---------------- helpers ----------------
__device__ __forceinline__ uint32_t smem_u32(const void* p) {
    uint32_t a;
    asm("{ .reg .u64 t; cvta.to.shared.u64 t, %1; cvt.u32.u64 %0, t; }" : "=r"(a) : "l"(p));
    return a;
}

#define LDSM4(r, addr) \
    asm volatile("ldmatrix.sync.aligned.m8n8.x4.shared.b16 {%0,%1,%2,%3}, [%4];" \
        : "=r"((r)[0]), "=r"((r)[1]), "=r"((r)[2]), "=r"((r)[3]) : "r"(addr))

#define MMA16816(c, a, b0v, b1v) \
    asm volatile("mma.sync.aligned.m16n8k16.row.col.f32.f16.f16.f32 " \
        "{%0,%1,%2,%3}, {%4,%5,%6,%7}, {%8,%9}, {%0,%1,%2,%3};" \
        : "+f"((c)[0]), "+f"((c)[1]), "+f"((c)[2]), "+f"((c)[3]) \
        : "r"((a)[0]), "r"((a)[1]), "r"((a)[2]), "r"((a)[3]), "r"(b0v), "r"(b1v))

#define CP_ASYNC16(dst, src) \
    asm volatile("cp.async.cg.shared.global [%0], [%1], 16;" :: "r"(dst), "l"(src))
#define CP_COMMIT  asm volatile("cp.async.commit_group;" ::: "memory")
#define CP_WAIT1   asm volatile("cp.async.wait_group 1;" ::: "memory")

__device__ __forceinline__ void wait_chunk(int ch) {
    if (!g_flag[ch]) {
        while (!g_flag[ch]) __nanosleep(256);
    }
    __threadfence();   // acquire: order g_af reads after flag observation
}

__device__ __forceinline__ int chunk_of_tile(int t) {
    int b = t * 8 + 7;                 // last gather block covering this tile
    if (b > 12499) b = 12499;          // pad tiles -> last chunk
    return b / CHB;
}

// ------- init counters + flags + dtype detection (fused) ------------------
__global__ void k_init(const unsigned int* __restrict__ e) {
    int i = blockIdx.x * blockDim.x + threadIdx.x;
    if (i < NN) { g_deg[i] = 0; g_cur[i] = 0; }
    if (i < NCHG) { g_cnt[i] = 0; g_flag[i] = 0; }
    if (i == 0) {
        int ok = 1;
#pragma unroll
        for (int q = 0; q < 64; q++) ok &= (e[2 * q + 1] == 0u);
        g_is64 = ok;   // all high words zero -> int64
    }
}

// ------- fold weights -> fp16 B image, z/t column-interleaved ------------
__global__ void k_wp(const float* __restrict__ Wz, const float* __restrict__ lzW,
                     const float* __restrict__ Wh, const float* __restrict__ lhW) {
    int k = blockIdx.x;        // 0..127 (GEMM K dim)
    int half = blockIdx.y;     // 0: z, 1: t
    int j = threadIdx.x;       // 0..127
    const float* W = half ? Wh : Wz;
    const float* L = half ? lhW : lzW;
    float acc = 0.f;
#pragma unroll 4
    for (int c = 0; c < DH; c++) acc += W[k * DH + c] * L[c * DH + j];
    int n = 2 * j + half;
    int off = n * 256 + (((k >> 3) ^ (n & 7)) << 4) + (k & 7) * 2;
    *(__half*)(g_bimg + off) = __float2half_rn(acc);
}

// ---------------- degree (dst only), 4 edges per thread -------------------
__global__ void k_deg(const void* __restrict__ e) {
    int t = blockIdx.x * blockDim.x + threadIdx.x;
    if (t >= NE / 4) return;
    int d0, d1, d2, d3;
    if (g_is64) {
        const ulonglong2* p = (const ulonglong2*)((const long long*)e + NE);
        ulonglong2 a = p[2 * t], b = p[2 * t + 1];
        d0 = (int)a.x; d1 = (int)a.y; d2 = (int)b.x; d3 = (int)b.y;
    } else {
        const int4* p = (const int4*)((const int*)e + NE);
        int4 a = p[t];
        d0 = a.x; d1 = a.y; d2 = a.z; d3 = a.w;
    }
    atomicAdd(&g_deg[d0], 1);
    atomicAdd(&g_deg[d1], 1);
    atomicAdd(&g_deg[d2], 1);
    atomicAdd(&g_deg[d3], 1);
}

// ------- fused dinv + xs: thread per 16B chunk, 4 independent iters -------
#define DX_STRIDE 800000
__global__ void __launch_bounds__(256) k_dinvxs(const float4* __restrict__ x4) {
    int base = blockIdx.x * blockDim.x + threadIdx.x;
#pragma unroll
    for (int k = 0; k < 4; k++) {
        int idx = base + k * DX_STRIDE;
        int node = idx >> 5;
        float di = rsqrtf((float)g_deg[node] + 2.0f);
        float4 v = __ldcs(&x4[idx]);
        __half2 h0 = __floats2half2_rn(v.x * di, v.y * di);
        __half2 h1 = __floats2half2_rn(v.z * di, v.w * di);
        uint2 o;
        o.x = *reinterpret_cast<uint32_t*>(&h0);
        o.y = *reinterpret_cast<uint32_t*>(&h1);
        *(uint2*)&g_xsh[(size_t)idx * 2] = o;
        if ((idx & 31) == 0) g_dinv[node] = di;
    }
}

// ---------------- prefix scan of degrees (3 phases) ----------------
__global__ void k_scan1() {
    __shared__ int sbuf[SCAN_B];
    int tid = threadIdx.x;
    int i = blockIdx.x * SCAN_B + tid;
    int v = (i < NN) ? g_deg[i] : 0;
    sbuf[tid] = v;
    __syncthreads();
#pragma unroll
    for (int ofs = 1; ofs < SCAN_B; ofs <<= 1) {
        int t = (tid >= ofs) ? sbuf[tid - ofs] : 0;
        __syncthreads();
        sbuf[tid] += t;
        __syncthreads();
    }
    g_scan[blockIdx.x * SCAN_B + tid] = sbuf[tid];
    if (tid == SCAN_B - 1) g_bsum[blockIdx.x] = sbuf[tid];
}

__global__ void k_scan2() {
    __shared__ int sb[128];
    int t = threadIdx.x;
    int v = (t < NB) ? g_bsum[t] : 0;
    sb[t] = v;
    __syncthreads();
#pragma unroll
    for (int o = 1; o < 128; o <<= 1) {
        int u = (t >= o) ? sb[t - o] : 0;
        __syncthreads();
        sb[t] += u;
        __syncthreads();
    }
    if (t < NB) g_boff[t] = sb[t] - v;   // exclusive prefix
}

__global__ void k_scan3() {
    int i = blockIdx.x * blockDim.x + threadIdx.x;
    if (i < NN) g_off[i] = g_scan[i] - g_deg[i] + g_boff[i >> 10];
    if (i == NN) g_off[NN] = NE;
}

// ---------------- fill CSR, 4 edges per thread ----------------
__global__ void k_fill(const void* __restrict__ e) {
    int t = blockIdx.x * blockDim.x + threadIdx.x;
    if (t >= NE / 4) return;
    int s0, s1, s2, s3, d0, d1, d2, d3;
    if (g_is64) {
        const ulonglong2* ps = (const ulonglong2*)e;
        const ulonglong2* pd = (const ulonglong2*)((const long long*)e + NE);
        ulonglong2 a0 = ps[2 * t], a1 = ps[2 * t + 1];
        ulonglong2 b0 = pd[2 * t], b1 = pd[2 * t + 1];
        s0 = (int)a0.x; s1 = (int)a0.y; s2 = (int)a1.x; s3 = (int)a1.y;
        d0 = (int)b0.x; d1 = (int)b0.y; d2 = (int)b1.x; d3 = (int)b1.y;
    } else {
        const int4* ps = (const int4*)e;
        const int4* pd = (const int4*)((const int*)e + NE);
        int4 a = ps[t], b = pd[t];
        s0 = a.x; s1 = a.y; s2 = a.z; s3 = a.w;
        d0 = b.x; d1 = b.y; d2 = b.z; d3 = b.w;
    }
    int p0 = atomicAdd(&g_cur[d0], 1); g_csr[g_off[d0] + p0] = s0;
    int p1 = atomicAdd(&g_cur[d1], 1); g_csr[g_off[d1] + p1] = s1;
    int p2 = atomicAdd(&g_cur[d2], 1); g_csr[g_off[d2] + p2] = s2;
    int p3 = atomicAdd(&g_cur[d3], 1); g_csr[g_off[d3] + p3] = s3;
}

// ---------------- gather -> fp16 A, with chunk-done signaling -------------
__device__ __forceinline__ void acc_h2pair(float4& a, uint2 raw) {
    float2 f0 = __half22float2(*reinterpret_cast<const __half2*>(&raw.x));
    float2 f1 = __half22float2(*reinterpret_cast<const __half2*>(&raw.y));
    a.x += f0.x; a.y += f0.y; a.z += f1.x; a.w += f1.y;
}

// grid = 12500 blocks x 256 threads, warp per node (exactly covers NN)
__global__ void __launch_bounds__(256) k_gather() {
    int n = (blockIdx.x * blockDim.x + threadIdx.x) >> 5;
    int lane = threadIdx.x & 31;
    {
        int j = g_off[n];
        int jend = g_off[n + 1];
        const uint2* xs = (const uint2*)g_xsh;
        float4 a0 = make_float4(0.f, 0.f, 0.f, 0.f);
        float4 a1 = make_float4(0.f, 0.f, 0.f, 0.f);
        {
            uint2 raw = xs[(long long)n * 32 + lane];
            acc_h2pair(a0, raw);
            a0.x *= 2.f; a0.y *= 2.f; a0.z *= 2.f; a0.w *= 2.f;
        }
        for (; j + 4 <= jend; j += 4) {
            int s0 = __ldcs(&g_csr[j]);
            int s1 = __ldcs(&g_csr[j + 1]);
            int s2 = __ldcs(&g_csr[j + 2]);
            int s3 = __ldcs(&g_csr[j + 3]);
            uint2 r0 = xs[(long long)s0 * 32 + lane];
            uint2 r1 = xs[(long long)s1 * 32 + lane];
            uint2 r2 = xs[(long long)s2 * 32 + lane];
            uint2 r3 = xs[(long long)s3 * 32 + lane];
            acc_h2pair(a0, r0);
            acc_h2pair(a1, r1);
            acc_h2pair(a0, r2);
            acc_h2pair(a1, r3);
        }
        for (; j < jend; j++) {
            int s = __ldcs(&g_csr[j]);
            uint2 r = xs[(long long)s * 32 + lane];
            acc_h2pair(a1, r);
        }
        float di = g_dinv[n];
        uint2 H;
        __half2 h0 = __floats2half2_rn(di * (a0.x + a1.x), di * (a0.y + a1.y));
        __half2 h1 = __floats2half2_rn(di * (a0.z + a1.z), di * (a0.w + a1.w));
        H.x = *reinterpret_cast<uint32_t*>(&h0);
        H.y = *reinterpret_cast<uint32_t*>(&h1);
        *(uint2*)&g_af[(size_t)n * DH + lane * 4] = H;
    }
    // chunk-done: last block of this chunk raises the flag
    __syncthreads();
    if (threadIdx.x == 0) {
        int ch = blockIdx.x / CHB;
        int tot = (ch == NCHG - 1) ? (12500 - (NCHG - 1) * CHB) : CHB;
        __threadfence();   // release: g_af writes before counter
        if (atomicAdd(&g_cnt[ch], 1) == tot - 1)
            g_flag[ch] = 1;
    }
}

// ---------------- HMMA GEMM (mma.sync fp16) + gate epilogue -------------
// SINGLE persistent launch, grid 148 (1 CTA/SM), overlaps with gather by
// spin-waiting on per-chunk flags before each tile's A prefetch.
#define SM_B  0
#define SM_A0 65536
#define SM_A1 81920
#define SM_PP 98304
#define SM_ZB 99328
#define SM_HB 99840
#define SM_W2 100352
#define GEMM_SMEM 100864

__global__ void __launch_bounds__(256, 2) k_gemm(
    const float* __restrict__ lzb, const float* __restrict__ lhb,
    const float* __restrict__ w2, const float* __restrict__ b2,
    float* __restrict__ out)
{
    extern __shared__ unsigned char smem[];
    uint32_t sb = smem_u32(smem);
    int tid = threadIdx.x;
    int lane = tid & 31;
    int warp = tid >> 5;
    int wm = warp & 1, wn = warp >> 1;     // 2 m-tiles x 4 n-tiles
    int m_base = wm * 32, n_base = wn * 64;
    int tid4 = lane & 3, grp = lane >> 2;

    float* p_part = (float*)(smem + SM_PP);
    float* szb = (float*)(smem + SM_ZB);
    float* shb = (float*)(smem + SM_HB);
    float* sw  = (float*)(smem + SM_W2);

    // load B image (pre-swizzled) + biases (ready: same-stream after k_wp)
    for (int i = tid * 16; i < 65536; i += 256 * 16)
        *(uint4*)(smem + i) = *(const uint4*)(g_bimg + i);
    if (tid < 128) { szb[tid] = lzb[tid]; shb[tid] = lhb[tid]; sw[tid] = w2[tid]; }
    float bbias = b2[0];

    // per-thread cp.async chunk indices (4 chunks of 16B per thread; 64 rows)
    uint32_t cp_dst[4];
    const __half* cp_src[4];
#pragma unroll
    for (int it = 0; it < 4; it++) {
        int idx = tid + it * 256;         // 0..1023
        int row = idx >> 4, cc = idx & 15;
        cp_dst[it] = (uint32_t)(row * 256 + ((cc ^ (row & 7)) << 4));
        cp_src[it] = g_af + (size_t)row * DH + cc * 8;
    }

    // ldmatrix lane address components
    int a_row = (lane & 7) | (((lane >> 3) & 1) << 3);
    int a_ks  = lane >> 4;
    int b_nrow = (lane & 7) | ((lane >> 4) << 3);
    int b_ks  = (lane >> 3) & 1;
    int swz = lane & 7;
    uint32_t aRow0 = (uint32_t)(m_base + a_row) * 256;
    uint32_t aRow1 = (uint32_t)(m_base + 16 + a_row) * 256;
    uint32_t bRow[4];
#pragma unroll
    for (int q = 0; q < 4; q++) bRow[q] = (uint32_t)(n_base + q * 16 + b_nrow) * 256;

    // prologue: wait for first tile's gather chunk, then prefetch into A0
    {
        wait_chunk(chunk_of_tile(blockIdx.x));
        size_t srcOfs = (size_t)(blockIdx.x << 6) * DH;
        uint32_t base = sb + SM_A0;
#pragma unroll
        for (int it = 0; it < 4; it++)
            CP_ASYNC16(base + cp_dst[it], cp_src[it] + srcOfs);
    }
    CP_COMMIT;
    __syncthreads();   // B image + biases ready

    int buf = 0;
    for (int tile = blockIdx.x; tile < NT64; tile += gridDim.x) {
        int rowBase = tile << 6;
        // prefetch next tile into other buffer (after its gather chunk lands)
        int nxt = tile + gridDim.x;
        if (nxt < NT64) {
            wait_chunk(chunk_of_tile(nxt));
            size_t srcOfs = (size_t)(nxt << 6) * DH;
            uint32_t base = sb + (buf ? SM_A0 : SM_A1);
#pragma unroll
            for (int it = 0; it < 4; it++)
                CP_ASYNC16(base + cp_dst[it], cp_src[it] + srcOfs);
        }
        CP_COMMIT;
        CP_WAIT1;          // current tile's group complete
        __syncthreads();

        uint32_t aS = sb + (buf ? SM_A1 : SM_A0);
        uint32_t bS = sb + SM_B;

        float c[2][8][4];
#pragma unroll
        for (int mt = 0; mt < 2; mt++)
#pragma unroll
            for (int nt = 0; nt < 8; nt++)
#pragma unroll
                for (int q = 0; q < 4; q++) c[mt][nt][q] = 0.f;

#pragma unroll
        for (int kt = 0; kt < 8; kt++) {
            int kc = kt * 2;
            uint32_t a0[4], a1[4], bfr[4][4];
            uint32_t aoff = (uint32_t)(((kc + a_ks) ^ swz) << 4);
            LDSM4(a0, aS + aRow0 + aoff);
            LDSM4(a1, aS + aRow1 + aoff);
            uint32_t boff = (uint32_t)(((kc + b_ks) ^ swz) << 4);
#pragma unroll
            for (int q = 0; q < 4; q++) LDSM4(bfr[q], bS + bRow[q] + boff);
#pragma unroll
            for (int nt = 0; nt < 8; nt++) {
                uint32_t b0v = bfr[nt >> 1][(nt & 1) * 2];
                uint32_t b1v = bfr[nt >> 1][(nt & 1) * 2 + 1];
                MMA16816(c[0][nt], a0, b0v, b1v);
                MMA16816(c[1][nt], a1, b0v, b1v);
            }
        }

        // gate epilogue (single-div form):
        // (1-sigmoid(z)) * tanh(t) = (e^{2t} - 1) / ((1 + e^{z}) (e^{2t} + 1))
        float pr[4] = {0.f, 0.f, 0.f, 0.f};
#pragma unroll
        for (int nt = 0; nt < 8; nt++) {
            int jj = (n_base >> 1) + nt * 4 + tid4;
            float zb = szb[jj], hb = shb[jj], w = sw[jj];
#pragma unroll
            for (int mt = 0; mt < 2; mt++) {
                {
                    float eu = __expf(c[mt][nt][0] + zb);
                    float e2 = __expf(2.f * (c[mt][nt][1] + hb));
                    float term = __fdividef(e2 - 1.f, (1.f + eu) * (e2 + 1.f));
                    pr[mt * 2 + 0] += term * w;
                }
                {
                    float eu = __expf(c[mt][nt][2] + zb);
                    float e2 = __expf(2.f * (c[mt][nt][3] + hb));
                    float term = __fdividef(e2 - 1.f, (1.f + eu) * (e2 + 1.f));
                    pr[mt * 2 + 1] += term * w;
                }
            }
        }
#pragma unroll
        for (int q = 0; q < 4; q++) {
            pr[q] += __shfl_xor_sync(0xffffffffu, pr[q], 1);
            pr[q] += __shfl_xor_sync(0xffffffffu, pr[q], 2);
        }
        if (tid4 == 0) {
            p_part[wn * 64 + m_base + grp]          = pr[0];
            p_part[wn * 64 + m_base + grp + 8]      = pr[1];
            p_part[wn * 64 + m_base + 16 + grp]     = pr[2];
            p_part[wn * 64 + m_base + 16 + grp + 8] = pr[3];
        }
        __syncthreads();
        if (tid < 64) {
            int row = rowBase + tid;
            if (row < NN)
                out[row] = p_part[tid] + p_part[64 + tid] +
                           p_part[128 + tid] + p_part[192 + tid] + bbias;
        }
        __syncthreads();
        buf ^= 1;
    }
}

// ---------------- launcher ----------------
// metadata order: x, edge_index, Wz, bz, Wr, br, Wh, bh,
//                 lzW, lzb, lrW, lrb, lhW, lhb, W2, b2
// s0: init, deg, scan1-3, fill, gather
// s2: wp (after init), dinvxs (after deg), gemm (spin-synced to gather flags)
extern "C" void kernel_launch(void* const* d_in, const int* in_sizes, int n_in,
                              void* d_out, int out_size) {
    const float4* x4  = (const float4*)d_in[0];
    const void*   ei  = d_in[1];
    const float*  Wz  = (const float*)d_in[2];
    const float*  Wh  = (const float*)d_in[6];
    const float*  lzW = (const float*)d_in[8];
    const float*  lzb = (const float*)d_in[9];
    const float*  lhW = (const float*)d_in[12];
    const float*  lhb = (const float*)d_in[13];
    const float*  W2  = (const float*)d_in[14];
    const float*  b2  = (const float*)d_in[15];
    float* out = (float*)d_out;

    cudaFuncSetAttribute(k_gemm, cudaFuncAttributeMaxDynamicSharedMemorySize, GEMM_SMEM);

    cudaStream_t s2 = 0;
    cudaEvent_t evStart = 0, evDeg = 0, evDinv = 0, evEnd = 0;
    bool forked = (cudaStreamCreateWithFlags(&s2, cudaStreamNonBlocking) == cudaSuccess);
    if (forked) {
        forked &= (cudaEventCreateWithFlags(&evStart, cudaEventDisableTiming) == cudaSuccess);
        forked &= (cudaEventCreateWithFlags(&evDeg,   cudaEventDisableTiming) == cudaSuccess);
        forked &= (cudaEventCreateWithFlags(&evDinv,  cudaEventDisableTiming) == cudaSuccess);
        forked &= (cudaEventCreateWithFlags(&evEnd,   cudaEventDisableTiming) == cudaSuccess);
    }

    if (forked) {
        k_init<<<(NN + 255) / 256, 256>>>((const unsigned int*)ei);
        cudaEventRecord(evStart, 0);
        cudaStreamWaitEvent(s2, evStart, 0);
        k_wp<<<dim3(DH, 2), DH, 0, s2>>>(Wz, lzW, Wh, lhW);

        k_deg<<<(NE / 4 + 255) / 256, 256>>>(ei);
        cudaEventRecord(evDeg, 0);
        cudaStreamWaitEvent(s2, evDeg, 0);
        k_dinvxs<<<DX_STRIDE / 256, 256, 0, s2>>>(x4);
        cudaEventRecord(evDinv, s2);
        // persistent GEMM: starts early, spins on gather chunk flags
        k_gemm<<<148, 256, GEMM_SMEM, s2>>>(lzb, lhb, W2, b2, out);
        cudaEventRecord(evEnd, s2);

        k_scan1<<<NB, SCAN_B>>>();
        k_scan2<<<1, 128>>>();
        k_scan3<<<(NN + 256) / 256, 256>>>();
        k_fill<<<(NE / 4 + 255) / 256, 256>>>(ei);
        cudaStreamWaitEvent(0, evDinv, 0);   // gather needs xsh + dinv
        k_gather<<<12500, 256>>>();

        cudaStreamWaitEvent(0, evEnd, 0);    // join gemm back to origin stream
    } else {
        k_init<<<(NN + 255) / 256, 256>>>((const unsigned int*)ei);
        k_wp<<<dim3(DH, 2), DH>>>(Wz, lzW, Wh, lhW);
        k_deg<<<(NE / 4 + 255) / 256, 256>>>(ei);
        k_dinvxs<<<DX_STRIDE / 256, 256>>>(x4);
        k_scan1<<<NB, SCAN_B>>>();
        k_scan2<<<1, 128>>>();
        k_scan3<<<(NN + 256) / 256, 256>>>();
        k_fill<<<(NE / 4 + 255) / 256, 256>>>(ei);
        k_gather<<<12500, 256>>>();
        k_gemm<<<148, 256, GEMM_SMEM>>>(lzb, lhb, W2, b2, out);
    }
}

// round 14
// speedup vs baseline: 1.0036x; 1.0036x over previous
#include <cuda_runtime.h>
#include <cuda_fp16.h>
#include <math.h>
#include <stdint.h>

#define NN 100000
#define NE 1600000
#define DH 128
#define NPAD 100096                  // padded rows (multiple of 128)
#define NT64 1564                    // NPAD / 64 tiles
#define SCAN_B 1024
#define NB ((NN + SCAN_B - 1) / SCAN_B)
#define NCHG 16                      // gather progress chunks
#define CHB 782                      // gather blocks per chunk (12500 = 15*782 + 770)

// ---------------- device scratch (no allocations allowed) ----------------
__device__ int     g_is64;
__device__ int     g_deg[NN];
__device__ int     g_cur[NN];
__device__ int     g_scan[NB * SCAN_B];
__device__ int     g_bsum[NB];
__device__ int     g_boff[NB];
__device__ int     g_off[NN + 1];
__device__ int     g_csr[NE];                         // src ids grouped by dst
__device__ float   g_dinv[NN];
__device__ __half2 g_xsh[(size_t)NN * 64];            // dinv-scaled x fp16, 25.6MB
__device__ __align__(16) __half g_af[(size_t)NPAD * DH];   // agg fp16 (pad rows stale, masked)
__device__ __align__(16) unsigned char g_bimg[65536];      // B fp16, [n][k] swizzled
__device__ volatile int g_flag[NCHG];                 // gather chunk-done flags
__device__ int     g_cnt[NCHG];                       // gather chunk block counters

// ---------------- helpers ----------------
__device__ __forceinline__ uint32_t smem_u32(const void* p) {
    uint32_t a;
    asm("{ .reg .u64 t; cvta.to.shared.u64 t, %1; cvt.u32.u64 %0, t; }" : "=r"(a) : "l"(p));
    return a;
}

#define LDSM4(r, addr) \
    asm volatile("ldmatrix.sync.aligned.m8n8.x4.shared.b16 {%0,%1,%2,%3}, [%4];" \
        : "=r"((r)[0]), "=r"((r)[1]), "=r"((r)[2]), "=r"((r)[3]) : "r"(addr))

#define MMA16816(c, a, b0v, b1v) \
    asm volatile("mma.sync.aligned.m16n8k16.row.col.f32.f16.f16.f32 " \
        "{%0,%1,%2,%3}, {%4,%5,%6,%7}, {%8,%9}, {%0,%1,%2,%3};" \
        : "+f"((c)[0]), "+f"((c)[1]), "+f"((c)[2]), "+f"((c)[3]) \
        : "r"((a)[0]), "r"((a)[1]), "r"((a)[2]), "r"((a)[3]), "r"(b0v), "r"(b1v))

#define CP_ASYNC16(dst, src) \
    asm volatile("cp.async.cg.shared.global [%0], [%1], 16;" :: "r"(dst), "l"(src))
#define CP_COMMIT  asm volatile("cp.async.commit_group;" ::: "memory")
#define CP_WAIT1   asm volatile("cp.async.wait_group 1;" ::: "memory")

// CTA-wide wait: ONLY thread 0 polls the flag (avoids L2 polling storm),
// then a block barrier releases everyone. cp.async.cg reads go to coherent
// L2, so data written before the release-flag is visible.
__device__ __forceinline__ void wait_chunk_cta(int ch) {
    if (threadIdx.x == 0) {
        while (!g_flag[ch]) __nanosleep(128);
        __threadfence();   // acquire
    }
    __syncthreads();
}

__device__ __forceinline__ int chunk_of_tile(int t) {
    int b = t * 8 + 7;                 // last gather block covering this tile
    if (b > 12499) b = 12499;          // pad tiles -> last chunk
    return b / CHB;
}

// ------- init counters + flags + dtype detection (fused) ------------------
__global__ void k_init(const unsigned int* __restrict__ e) {
    int i = blockIdx.x * blockDim.x + threadIdx.x;
    if (i < NN) { g_deg[i] = 0; g_cur[i] = 0; }
    if (i < NCHG) { g_cnt[i] = 0; g_flag[i] = 0; }
    if (i == 0) {
        int ok = 1;
#pragma unroll
        for (int q = 0; q < 64; q++) ok &= (e[2 * q + 1] == 0u);
        g_is64 = ok;   // all high words zero -> int64
    }
}

// ------- fold weights -> fp16 B image, z/t column-interleaved ------------
__global__ void k_wp(const float* __restrict__ Wz, const float* __restrict__ lzW,
                     const float* __restrict__ Wh, const float* __restrict__ lhW) {
    int k = blockIdx.x;        // 0..127 (GEMM K dim)
    int half = blockIdx.y;     // 0: z, 1: t
    int j = threadIdx.x;       // 0..127
    const float* W = half ? Wh : Wz;
    const float* L = half ? lhW : lzW;
    float acc = 0.f;
#pragma unroll 4
    for (int c = 0; c < DH; c++) acc += W[k * DH + c] * L[c * DH + j];
    int n = 2 * j + half;
    int off = n * 256 + (((k >> 3) ^ (n & 7)) << 4) + (k & 7) * 2;
    *(__half*)(g_bimg + off) = __float2half_rn(acc);
}

// ---------------- degree (dst only), 4 edges per thread -------------------
__global__ void k_deg(const void* __restrict__ e) {
    int t = blockIdx.x * blockDim.x + threadIdx.x;
    if (t >= NE / 4) return;
    int d0, d1, d2, d3;
    if (g_is64) {
        const ulonglong2* p = (const ulonglong2*)((const long long*)e + NE);
        ulonglong2 a = p[2 * t], b = p[2 * t + 1];
        d0 = (int)a.x; d1 = (int)a.y; d2 = (int)b.x; d3 = (int)b.y;
    } else {
        const int4* p = (const int4*)((const int*)e + NE);
        int4 a = p[t];
        d0 = a.x; d1 = a.y; d2 = a.z; d3 = a.w;
    }
    atomicAdd(&g_deg[d0], 1);
    atomicAdd(&g_deg[d1], 1);
    atomicAdd(&g_deg[d2], 1);
    atomicAdd(&g_deg[d3], 1);
}

// ------- fused dinv + xs: thread per 16B chunk, 4 independent iters -------
#define DX_STRIDE 800000
__global__ void __launch_bounds__(256) k_dinvxs(const float4* __restrict__ x4) {
    int base = blockIdx.x * blockDim.x + threadIdx.x;
#pragma unroll
    for (int k = 0; k < 4; k++) {
        int idx = base + k * DX_STRIDE;
        int node = idx >> 5;
        float di = rsqrtf((float)g_deg[node] + 2.0f);
        float4 v = __ldcs(&x4[idx]);
        __half2 h0 = __floats2half2_rn(v.x * di, v.y * di);
        __half2 h1 = __floats2half2_rn(v.z * di, v.w * di);
        uint2 o;
        o.x = *reinterpret_cast<uint32_t*>(&h0);
        o.y = *reinterpret_cast<uint32_t*>(&h1);
        *(uint2*)&g_xsh[(size_t)idx * 2] = o;
        if ((idx & 31) == 0) g_dinv[node] = di;
    }
}

// ---------------- prefix scan of degrees (3 phases) ----------------
__global__ void k_scan1() {
    __shared__ int sbuf[SCAN_B];
    int tid = threadIdx.x;
    int i = blockIdx.x * SCAN_B + tid;
    int v = (i < NN) ? g_deg[i] : 0;
    sbuf[tid] = v;
    __syncthreads();
#pragma unroll
    for (int ofs = 1; ofs < SCAN_B; ofs <<= 1) {
        int t = (tid >= ofs) ? sbuf[tid - ofs] : 0;
        __syncthreads();
        sbuf[tid] += t;
        __syncthreads();
    }
    g_scan[blockIdx.x * SCAN_B + tid] = sbuf[tid];
    if (tid == SCAN_B - 1) g_bsum[blockIdx.x] = sbuf[tid];
}

__global__ void k_scan2() {
    __shared__ int sb[128];
    int t = threadIdx.x;
    int v = (t < NB) ? g_bsum[t] : 0;
    sb[t] = v;
    __syncthreads();
#pragma unroll
    for (int o = 1; o < 128; o <<= 1) {
        int u = (t >= o) ? sb[t - o] : 0;
        __syncthreads();
        sb[t] += u;
        __syncthreads();
    }
    if (t < NB) g_boff[t] = sb[t] - v;   // exclusive prefix
}

__global__ void k_scan3() {
    int i = blockIdx.x * blockDim.x + threadIdx.x;
    if (i < NN) g_off[i] = g_scan[i] - g_deg[i] + g_boff[i >> 10];
    if (i == NN) g_off[NN] = NE;
}

// ---------------- fill CSR, 4 edges per thread ----------------
__global__ void k_fill(const void* __restrict__ e) {
    int t = blockIdx.x * blockDim.x + threadIdx.x;
    if (t >= NE / 4) return;
    int s0, s1, s2, s3, d0, d1, d2, d3;
    if (g_is64) {
        const ulonglong2* ps = (const ulonglong2*)e;
        const ulonglong2* pd = (const ulonglong2*)((const long long*)e + NE);
        ulonglong2 a0 = ps[2 * t], a1 = ps[2 * t + 1];
        ulonglong2 b0 = pd[2 * t], b1 = pd[2 * t + 1];
        s0 = (int)a0.x; s1 = (int)a0.y; s2 = (int)a1.x; s3 = (int)a1.y;
        d0 = (int)b0.x; d1 = (int)b0.y; d2 = (int)b1.x; d3 = (int)b1.y;
    } else {
        const int4* ps = (const int4*)e;
        const int4* pd = (const int4*)((const int*)e + NE);
        int4 a = ps[t], b = pd[t];
        s0 = a.x; s1 = a.y; s2 = a.z; s3 = a.w;
        d0 = b.x; d1 = b.y; d2 = b.z; d3 = b.w;
    }
    int p0 = atomicAdd(&g_cur[d0], 1); g_csr[g_off[d0] + p0] = s0;
    int p1 = atomicAdd(&g_cur[d1], 1); g_csr[g_off[d1] + p1] = s1;
    int p2 = atomicAdd(&g_cur[d2], 1); g_csr[g_off[d2] + p2] = s2;
    int p3 = atomicAdd(&g_cur[d3], 1); g_csr[g_off[d3] + p3] = s3;
}

// ---------------- gather -> fp16 A, with chunk-done signaling -------------
__device__ __forceinline__ void acc_h2pair(float4& a, uint2 raw) {
    float2 f0 = __half22float2(*reinterpret_cast<const __half2*>(&raw.x));
    float2 f1 = __half22float2(*reinterpret_cast<const __half2*>(&raw.y));
    a.x += f0.x; a.y += f0.y; a.z += f1.x; a.w += f1.y;
}

// grid = 12500 blocks x 256 threads, warp per node (exactly covers NN)
__global__ void __launch_bounds__(256) k_gather() {
    int n = (blockIdx.x * blockDim.x + threadIdx.x) >> 5;
    int lane = threadIdx.x & 31;
    {
        int j = g_off[n];
        int jend = g_off[n + 1];
        const uint2* xs = (const uint2*)g_xsh;
        float4 a0 = make_float4(0.f, 0.f, 0.f, 0.f);
        float4 a1 = make_float4(0.f, 0.f, 0.f, 0.f);
        {
            uint2 raw = xs[(long long)n * 32 + lane];
            acc_h2pair(a0, raw);
            a0.x *= 2.f; a0.y *= 2.f; a0.z *= 2.f; a0.w *= 2.f;
        }
        for (; j + 4 <= jend; j += 4) {
            int s0 = __ldcs(&g_csr[j]);
            int s1 = __ldcs(&g_csr[j + 1]);
            int s2 = __ldcs(&g_csr[j + 2]);
            int s3 = __ldcs(&g_csr[j + 3]);
            uint2 r0 = xs[(long long)s0 * 32 + lane];
            uint2 r1 = xs[(long long)s1 * 32 + lane];
            uint2 r2 = xs[(long long)s2 * 32 + lane];
            uint2 r3 = xs[(long long)s3 * 32 + lane];
            acc_h2pair(a0, r0);
            acc_h2pair(a1, r1);
            acc_h2pair(a0, r2);
            acc_h2pair(a1, r3);
        }
        for (; j < jend; j++) {
            int s = __ldcs(&g_csr[j]);
            uint2 r = xs[(long long)s * 32 + lane];
            acc_h2pair(a1, r);
        }
        float di = g_dinv[n];
        uint2 H;
        __half2 h0 = __floats2half2_rn(di * (a0.x + a1.x), di * (a0.y + a1.y));
        __half2 h1 = __floats2half2_rn(di * (a0.z + a1.z), di * (a0.w + a1.w));
        H.x = *reinterpret_cast<uint32_t*>(&h0);
        H.y = *reinterpret_cast<uint32_t*>(&h1);
        *(uint2*)&g_af[(size_t)n * DH + lane * 4] = H;
    }
    // chunk-done: last block of this chunk raises the flag
    __syncthreads();
    if (threadIdx.x == 0) {
        int ch = blockIdx.x / CHB;
        int tot = (ch == NCHG - 1) ? (12500 - (NCHG - 1) * CHB) : CHB;
        __threadfence();   // release: g_af writes before counter
        if (atomicAdd(&g_cnt[ch], 1) == tot - 1)
            g_flag[ch] = 1;
    }
}

// ---------------- HMMA GEMM (mma.sync fp16) + gate epilogue -------------
// SINGLE persistent launch (after fill, concurrent with gather only),
// grid 148, spin-syncs (thread 0 only) on gather chunk flags per tile.
#define SM_B  0
#define SM_A0 65536
#define SM_A1 81920
#define SM_PP 98304
#define SM_ZB 99328
#define SM_HB 99840
#define SM_W2 100352
#define GEMM_SMEM 100864

__global__ void __launch_bounds__(256, 2) k_gemm(
    const float* __restrict__ lzb, const float* __restrict__ lhb,
    const float* __restrict__ w2, const float* __restrict__ b2,
    float* __restrict__ out)
{
    extern __shared__ unsigned char smem[];
    uint32_t sb = smem_u32(smem);
    int tid = threadIdx.x;
    int lane = tid & 31;
    int warp = tid >> 5;
    int wm = warp & 1, wn = warp >> 1;     // 2 m-tiles x 4 n-tiles
    int m_base = wm * 32, n_base = wn * 64;
    int tid4 = lane & 3, grp = lane >> 2;

    float* p_part = (float*)(smem + SM_PP);
    float* szb = (float*)(smem + SM_ZB);
    float* shb = (float*)(smem + SM_HB);
    float* sw  = (float*)(smem + SM_W2);

    // load B image (pre-swizzled) + biases
    for (int i = tid * 16; i < 65536; i += 256 * 16)
        *(uint4*)(smem + i) = *(const uint4*)(g_bimg + i);
    if (tid < 128) { szb[tid] = lzb[tid]; shb[tid] = lhb[tid]; sw[tid] = w2[tid]; }
    float bbias = b2[0];

    // per-thread cp.async chunk indices (4 chunks of 16B per thread; 64 rows)
    uint32_t cp_dst[4];
    const __half* cp_src[4];
#pragma unroll
    for (int it = 0; it < 4; it++) {
        int idx = tid + it * 256;         // 0..1023
        int row = idx >> 4, cc = idx & 15;
        cp_dst[it] = (uint32_t)(row * 256 + ((cc ^ (row & 7)) << 4));
        cp_src[it] = g_af + (size_t)row * DH + cc * 8;
    }

    // ldmatrix lane address components
    int a_row = (lane & 7) | (((lane >> 3) & 1) << 3);
    int a_ks  = lane >> 4;
    int b_nrow = (lane & 7) | ((lane >> 4) << 3);
    int b_ks  = (lane >> 3) & 1;
    int swz = lane & 7;
    uint32_t aRow0 = (uint32_t)(m_base + a_row) * 256;
    uint32_t aRow1 = (uint32_t)(m_base + 16 + a_row) * 256;
    uint32_t bRow[4];
#pragma unroll
    for (int q = 0; q < 4; q++) bRow[q] = (uint32_t)(n_base + q * 16 + b_nrow) * 256;

    // prologue: wait for first tile's gather chunk, then prefetch into A0
    wait_chunk_cta(chunk_of_tile(blockIdx.x));
    {
        size_t srcOfs = (size_t)(blockIdx.x << 6) * DH;
        uint32_t base = sb + SM_A0;
#pragma unroll
        for (int it = 0; it < 4; it++)
            CP_ASYNC16(base + cp_dst[it], cp_src[it] + srcOfs);
    }
    CP_COMMIT;
    __syncthreads();   // B image + biases ready

    int buf = 0;
    for (int tile = blockIdx.x; tile < NT64; tile += gridDim.x) {
        int rowBase = tile << 6;
        // prefetch next tile into other buffer (after its gather chunk lands)
        int nxt = tile + gridDim.x;
        if (nxt < NT64) {
            wait_chunk_cta(chunk_of_tile(nxt));
            size_t srcOfs = (size_t)(nxt << 6) * DH;
            uint32_t base = sb + (buf ? SM_A0 : SM_A1);
#pragma unroll
            for (int it = 0; it < 4; it++)
                CP_ASYNC16(base + cp_dst[it], cp_src[it] + srcOfs);
        }
        CP_COMMIT;
        CP_WAIT1;          // current tile's group complete
        __syncthreads();

        uint32_t aS = sb + (buf ? SM_A1 : SM_A0);
        uint32_t bS = sb + SM_B;

        float c[2][8][4];
#pragma unroll
        for (int mt = 0; mt < 2; mt++)
#pragma unroll
            for (int nt = 0; nt < 8; nt++)
#pragma unroll
                for (int q = 0; q < 4; q++) c[mt][nt][q] = 0.f;

#pragma unroll
        for (int kt = 0; kt < 8; kt++) {
            int kc = kt * 2;
            uint32_t a0[4], a1[4], bfr[4][4];
            uint32_t aoff = (uint32_t)(((kc + a_ks) ^ swz) << 4);
            LDSM4(a0, aS + aRow0 + aoff);
            LDSM4(a1, aS + aRow1 + aoff);
            uint32_t boff = (uint32_t)(((kc + b_ks) ^ swz) << 4);
#pragma unroll
            for (int q = 0; q < 4; q++) LDSM4(bfr[q], bS + bRow[q] + boff);
#pragma unroll
            for (int nt = 0; nt < 8; nt++) {
                uint32_t b0v = bfr[nt >> 1][(nt & 1) * 2];
                uint32_t b1v = bfr[nt >> 1][(nt & 1) * 2 + 1];
                MMA16816(c[0][nt], a0, b0v, b1v);
                MMA16816(c[1][nt], a1, b0v, b1v);
            }
        }

        // gate epilogue (single-div form):
        // (1-sigmoid(z)) * tanh(t) = (e^{2t} - 1) / ((1 + e^{z}) (e^{2t} + 1))
        float pr[4] = {0.f, 0.f, 0.f, 0.f};
#pragma unroll
        for (int nt = 0; nt < 8; nt++) {
            int jj = (n_base >> 1) + nt * 4 + tid4;
            float zb = szb[jj], hb = shb[jj], w = sw[jj];
#pragma unroll
            for (int mt = 0; mt < 2; mt++) {
                {
                    float eu = __expf(c[mt][nt][0] + zb);
                    float e2 = __expf(2.f * (c[mt][nt][1] + hb));
                    float term = __fdividef(e2 - 1.f, (1.f + eu) * (e2 + 1.f));
                    pr[mt * 2 + 0] += term * w;
                }
                {
                    float eu = __expf(c[mt][nt][2] + zb);
                    float e2 = __expf(2.f * (c[mt][nt][3] + hb));
                    float term = __fdividef(e2 - 1.f, (1.f + eu) * (e2 + 1.f));
                    pr[mt * 2 + 1] += term * w;
                }
            }
        }
#pragma unroll
        for (int q = 0; q < 4; q++) {
            pr[q] += __shfl_xor_sync(0xffffffffu, pr[q], 1);
            pr[q] += __shfl_xor_sync(0xffffffffu, pr[q], 2);
        }
        if (tid4 == 0) {
            p_part[wn * 64 + m_base + grp]          = pr[0];
            p_part[wn * 64 + m_base + grp + 8]      = pr[1];
            p_part[wn * 64 + m_base + 16 + grp]     = pr[2];
            p_part[wn * 64 + m_base + 16 + grp + 8] = pr[3];
        }
        __syncthreads();
        if (tid < 64) {
            int row = rowBase + tid;
            if (row < NN)
                out[row] = p_part[tid] + p_part[64 + tid] +
                           p_part[128 + tid] + p_part[192 + tid] + bbias;
        }
        __syncthreads();
        buf ^= 1;
    }
}

// ---------------- launcher ----------------
// metadata order: x, edge_index, Wz, bz, Wr, br, Wh, bh,
//                 lzW, lzb, lrW, lrb, lhW, lhb, W2, b2
// s0: init, deg, scan1-3, fill, gather
// s2: wp (after init), dinvxs (after deg), gemm (AFTER fill; overlaps gather
//     via single-thread chunk-flag spin).
extern "C" void kernel_launch(void* const* d_in, const int* in_sizes, int n_in,
                              void* d_out, int out_size) {
    const float4* x4  = (const float4*)d_in[0];
    const void*   ei  = d_in[1];
    const float*  Wz  = (const float*)d_in[2];
    const float*  Wh  = (const float*)d_in[6];
    const float*  lzW = (const float*)d_in[8];
    const float*  lzb = (const float*)d_in[9];
    const float*  lhW = (const float*)d_in[12];
    const float*  lhb = (const float*)d_in[13];
    const float*  W2  = (const float*)d_in[14];
    const float*  b2  = (const float*)d_in[15];
    float* out = (float*)d_out;

    cudaFuncSetAttribute(k_gemm, cudaFuncAttributeMaxDynamicSharedMemorySize, GEMM_SMEM);

    cudaStream_t s2 = 0;
    cudaEvent_t evStart = 0, evDeg = 0, evDinv = 0, evFill = 0, evEnd = 0;
    bool forked = (cudaStreamCreateWithFlags(&s2, cudaStreamNonBlocking) == cudaSuccess);
    if (forked) {
        forked &= (cudaEventCreateWithFlags(&evStart, cudaEventDisableTiming) == cudaSuccess);
        forked &= (cudaEventCreateWithFlags(&evDeg,   cudaEventDisableTiming) == cudaSuccess);
        forked &= (cudaEventCreateWithFlags(&evDinv,  cudaEventDisableTiming) == cudaSuccess);
        forked &= (cudaEventCreateWithFlags(&evFill,  cudaEventDisableTiming) == cudaSuccess);
        forked &= (cudaEventCreateWithFlags(&evEnd,   cudaEventDisableTiming) == cudaSuccess);
    }

    if (forked) {
        k_init<<<(NN + 255) / 256, 256>>>((const unsigned int*)ei);
        cudaEventRecord(evStart, 0);
        cudaStreamWaitEvent(s2, evStart, 0);
        k_wp<<<dim3(DH, 2), DH, 0, s2>>>(Wz, lzW, Wh, lhW);

        k_deg<<<(NE / 4 + 255) / 256, 256>>>(ei);
        cudaEventRecord(evDeg, 0);
        cudaStreamWaitEvent(s2, evDeg, 0);
        k_dinvxs<<<DX_STRIDE / 256, 256, 0, s2>>>(x4);
        cudaEventRecord(evDinv, s2);

        k_scan1<<<NB, SCAN_B>>>();
        k_scan2<<<1, 128>>>();
        k_scan3<<<(NN + 256) / 256, 256>>>();
        k_fill<<<(NE / 4 + 255) / 256, 256>>>(ei);
        cudaEventRecord(evFill, 0);

        // gemm on s2 only after fill: co-resident with gather alone
        cudaStreamWaitEvent(s2, evFill, 0);
        k_gemm<<<148, 256, GEMM_SMEM, s2>>>(lzb, lhb, W2, b2, out);
        cudaEventRecord(evEnd, s2);

        cudaStreamWaitEvent(0, evDinv, 0);   // gather needs xsh + dinv
        k_gather<<<12500, 256>>>();

        cudaStreamWaitEvent(0, evEnd, 0);    // join gemm back to origin stream
    } else {
        k_init<<<(NN + 255) / 256, 256>>>((const unsigned int*)ei);
        k_wp<<<dim3(DH, 2), DH>>>(Wz, lzW, Wh, lhW);
        k_deg<<<(NE / 4 + 255) / 256, 256>>>(ei);
        k_dinvxs<<<DX_STRIDE / 256, 256>>>(x4);
        k_scan1<<<NB, SCAN_B>>>();
        k_scan2<<<1, 128>>>();
        k_scan3<<<(NN + 256) / 256, 256>>>();
        k_fill<<<(NE / 4 + 255) / 256, 256>>>(ei);
        k_gather<<<12500, 256>>>();
        k_gemm<<<148, 256, GEMM_SMEM>>>(lzb, lhb, W2, b2, out);
    }
}

// round 15
// speedup vs baseline: 1.1920x; 1.1877x over previous
#include <cuda_runtime.h>
#include <cuda_fp16.h>
#include <math.h>
#include <stdint.h>

#define NN 100000
#define NE 1600000
#define DH 128
#define NPAD 100096                  // padded rows (multiple of 128)
#define NT64 1564                    // NPAD / 64 tiles
#define SCAN_B 1024
#define NB ((NN + SCAN_B - 1) / SCAN_B)

// ---------------- device scratch (no allocations allowed) ----------------
__device__ int     g_is64;
__device__ int     g_deg[NN];
__device__ int     g_cur[NN];
__device__ int     g_scan[NB * SCAN_B];
__device__ int     g_bsum[NB];
__device__ int     g_boff[NB];
__device__ int     g_off[NN + 1];
__device__ int     g_csr[NE];                         // src ids grouped by dst
__device__ float   g_dinv[NN];
__device__ __half2 g_xsh[(size_t)NN * 64];            // dinv-scaled x fp16, 25.6MB
__device__ __align__(16) __half g_af[(size_t)NPAD * DH];   // agg fp16 (pad rows 0)
__device__ __align__(16) unsigned char g_bimg[65536];      // B fp16, [n][k] swizzled

// ---------------- helpers ----------------
__device__ __forceinline__ uint32_t smem_u32(const void* p) {
    uint32_t a;
    asm("{ .reg .u64 t; cvta.to.shared.u64 t, %1; cvt.u32.u64 %0, t; }" : "=r"(a) : "l"(p));
    return a;
}

#define LDSM4(r, addr) \
    asm volatile("ldmatrix.sync.aligned.m8n8.x4.shared.b16 {%0,%1,%2,%3}, [%4];" \
        : "=r"((r)[0]), "=r"((r)[1]), "=r"((r)[2]), "=r"((r)[3]) : "r"(addr))

#define MMA16816(c, a, b0v, b1v) \
    asm volatile("mma.sync.aligned.m16n8k16.row.col.f32.f16.f16.f32 " \
        "{%0,%1,%2,%3}, {%4,%5,%6,%7}, {%8,%9}, {%0,%1,%2,%3};" \
        : "+f"((c)[0]), "+f"((c)[1]), "+f"((c)[2]), "+f"((c)[3]) \
        : "r"((a)[0]), "r"((a)[1]), "r"((a)[2]), "r"((a)[3]), "r"(b0v), "r"(b1v))

#define CP_ASYNC16(dst, src) \
    asm volatile("cp.async.cg.shared.global [%0], [%1], 16;" :: "r"(dst), "l"(src))
#define CP_COMMIT  asm volatile("cp.async.commit_group;" ::: "memory")
#define CP_WAIT1   asm volatile("cp.async.wait_group 1;" ::: "memory")

// ------- init counters + dtype detection (fused) --------------------------
__global__ void k_init(const unsigned int* __restrict__ e) {
    int i = blockIdx.x * blockDim.x + threadIdx.x;
    if (i < NN) { g_deg[i] = 0; g_cur[i] = 0; }
    if (i == 0) {
        int ok = 1;
#pragma unroll
        for (int q = 0; q < 64; q++) ok &= (e[2 * q + 1] == 0u);
        g_is64 = ok;   // all high words zero -> int64
    }
}

// ------- fold weights -> fp16 B image, z/t column-interleaved ------------
__global__ void k_wp(const float* __restrict__ Wz, const float* __restrict__ lzW,
                     const float* __restrict__ Wh, const float* __restrict__ lhW) {
    int k = blockIdx.x;        // 0..127 (GEMM K dim)
    int half = blockIdx.y;     // 0: z, 1: t
    int j = threadIdx.x;       // 0..127
    const float* W = half ? Wh : Wz;
    const float* L = half ? lhW : lzW;
    float acc = 0.f;
#pragma unroll 4
    for (int c = 0; c < DH; c++) acc += W[k * DH + c] * L[c * DH + j];
    int n = 2 * j + half;
    int off = n * 256 + (((k >> 3) ^ (n & 7)) << 4) + (k & 7) * 2;
    *(__half*)(g_bimg + off) = __float2half_rn(acc);
}

// ---------------- degree (dst only), 8 edges per thread -------------------
__global__ void k_deg(const void* __restrict__ e) {
    int t = blockIdx.x * blockDim.x + threadIdx.x;
    if (t >= NE / 8) return;
    int d[8];
    if (g_is64) {
        const ulonglong2* p = (const ulonglong2*)((const long long*)e + NE);
#pragma unroll
        for (int q = 0; q < 4; q++) {
            ulonglong2 a = p[4 * t + q];
            d[2 * q] = (int)a.x; d[2 * q + 1] = (int)a.y;
        }
    } else {
        const int4* p = (const int4*)((const int*)e + NE);
#pragma unroll
        for (int q = 0; q < 2; q++) {
            int4 a = p[2 * t + q];
            d[4 * q] = a.x; d[4 * q + 1] = a.y; d[4 * q + 2] = a.z; d[4 * q + 3] = a.w;
        }
    }
#pragma unroll
    for (int q = 0; q < 8; q++) atomicAdd(&g_deg[d[q]], 1);
}

// ------- fused dinv + xs: thread per 16B chunk, 4 independent iters -------
#define DX_STRIDE 800000
__global__ void __launch_bounds__(256) k_dinvxs(const float4* __restrict__ x4) {
    int base = blockIdx.x * blockDim.x + threadIdx.x;
#pragma unroll
    for (int k = 0; k < 4; k++) {
        int idx = base + k * DX_STRIDE;
        int node = idx >> 5;
        float di = rsqrtf((float)g_deg[node] + 2.0f);
        float4 v = __ldcs(&x4[idx]);
        __half2 h0 = __floats2half2_rn(v.x * di, v.y * di);
        __half2 h1 = __floats2half2_rn(v.z * di, v.w * di);
        uint2 o;
        o.x = *reinterpret_cast<uint32_t*>(&h0);
        o.y = *reinterpret_cast<uint32_t*>(&h1);
        *(uint2*)&g_xsh[(size_t)idx * 2] = o;
        if ((idx & 31) == 0) g_dinv[node] = di;
    }
}

// ---------------- prefix scan of degrees (3 phases) ----------------
__global__ void k_scan1() {
    __shared__ int sbuf[SCAN_B];
    int tid = threadIdx.x;
    int i = blockIdx.x * SCAN_B + tid;
    int v = (i < NN) ? g_deg[i] : 0;
    sbuf[tid] = v;
    __syncthreads();
#pragma unroll
    for (int ofs = 1; ofs < SCAN_B; ofs <<= 1) {
        int t = (tid >= ofs) ? sbuf[tid - ofs] : 0;
        __syncthreads();
        sbuf[tid] += t;
        __syncthreads();
    }
    g_scan[blockIdx.x * SCAN_B + tid] = sbuf[tid];
    if (tid == SCAN_B - 1) g_bsum[blockIdx.x] = sbuf[tid];
}

__global__ void k_scan2() {
    __shared__ int sb[128];
    int t = threadIdx.x;
    int v = (t < NB) ? g_bsum[t] : 0;
    sb[t] = v;
    __syncthreads();
#pragma unroll
    for (int o = 1; o < 128; o <<= 1) {
        int u = (t >= o) ? sb[t - o] : 0;
        __syncthreads();
        sb[t] += u;
        __syncthreads();
    }
    if (t < NB) g_boff[t] = sb[t] - v;   // exclusive prefix
}

__global__ void k_scan3() {
    int i = blockIdx.x * blockDim.x + threadIdx.x;
    if (i < NN) g_off[i] = g_scan[i] - g_deg[i] + g_boff[i >> 10];
    if (i == NN) g_off[NN] = NE;
}

// ---------------- fill CSR, 4 edges per thread ----------------
__global__ void k_fill(const void* __restrict__ e) {
    int t = blockIdx.x * blockDim.x + threadIdx.x;
    if (t >= NE / 4) return;
    int s0, s1, s2, s3, d0, d1, d2, d3;
    if (g_is64) {
        const ulonglong2* ps = (const ulonglong2*)e;
        const ulonglong2* pd = (const ulonglong2*)((const long long*)e + NE);
        ulonglong2 a0 = ps[2 * t], a1 = ps[2 * t + 1];
        ulonglong2 b0 = pd[2 * t], b1 = pd[2 * t + 1];
        s0 = (int)a0.x; s1 = (int)a0.y; s2 = (int)a1.x; s3 = (int)a1.y;
        d0 = (int)b0.x; d1 = (int)b0.y; d2 = (int)b1.x; d3 = (int)b1.y;
    } else {
        const int4* ps = (const int4*)e;
        const int4* pd = (const int4*)((const int*)e + NE);
        int4 a = ps[t], b = pd[t];
        s0 = a.x; s1 = a.y; s2 = a.z; s3 = a.w;
        d0 = b.x; d1 = b.y; d2 = b.z; d3 = b.w;
    }
    int p0 = atomicAdd(&g_cur[d0], 1); g_csr[g_off[d0] + p0] = s0;
    int p1 = atomicAdd(&g_cur[d1], 1); g_csr[g_off[d1] + p1] = s1;
    int p2 = atomicAdd(&g_cur[d2], 1); g_csr[g_off[d2] + p2] = s2;
    int p3 = atomicAdd(&g_cur[d3], 1); g_csr[g_off[d3] + p3] = s3;
}

// ---------------- gather -> fp16 A ----------------
__device__ __forceinline__ void acc_h2pair(float4& a, uint2 raw) {
    float2 f0 = __half22float2(*reinterpret_cast<const __half2*>(&raw.x));
    float2 f1 = __half22float2(*reinterpret_cast<const __half2*>(&raw.y));
    a.x += f0.x; a.y += f0.y; a.z += f1.x; a.w += f1.y;
}

__global__ void __launch_bounds__(256) k_gather() {
    int n = (blockIdx.x * blockDim.x + threadIdx.x) >> 5;
    int lane = threadIdx.x & 31;
    if (n >= NN) return;
    int j = g_off[n];
    int jend = g_off[n + 1];
    const uint2* xs = (const uint2*)g_xsh;
    float4 a0 = make_float4(0.f, 0.f, 0.f, 0.f);
    float4 a1 = make_float4(0.f, 0.f, 0.f, 0.f);
    {
        uint2 raw = xs[(long long)n * 32 + lane];
        acc_h2pair(a0, raw);
        a0.x *= 2.f; a0.y *= 2.f; a0.z *= 2.f; a0.w *= 2.f;
    }
    for (; j + 4 <= jend; j += 4) {
        int s0 = __ldcs(&g_csr[j]);
        int s1 = __ldcs(&g_csr[j + 1]);
        int s2 = __ldcs(&g_csr[j + 2]);
        int s3 = __ldcs(&g_csr[j + 3]);
        uint2 r0 = xs[(long long)s0 * 32 + lane];
        uint2 r1 = xs[(long long)s1 * 32 + lane];
        uint2 r2 = xs[(long long)s2 * 32 + lane];
        uint2 r3 = xs[(long long)s3 * 32 + lane];
        acc_h2pair(a0, r0);
        acc_h2pair(a1, r1);
        acc_h2pair(a0, r2);
        acc_h2pair(a1, r3);
    }
    for (; j < jend; j++) {
        int s = __ldcs(&g_csr[j]);
        uint2 r = xs[(long long)s * 32 + lane];
        acc_h2pair(a1, r);
    }
    float di = g_dinv[n];
    uint2 H;
    __half2 h0 = __floats2half2_rn(di * (a0.x + a1.x), di * (a0.y + a1.y));
    __half2 h1 = __floats2half2_rn(di * (a0.z + a1.z), di * (a0.w + a1.w));
    H.x = *reinterpret_cast<uint32_t*>(&h0);
    H.y = *reinterpret_cast<uint32_t*>(&h1);
    *(uint2*)&g_af[(size_t)n * DH + lane * 4] = H;
}

// ---------------- HMMA GEMM (mma.sync fp16) + gate epilogue -------------
// persistent, 256 threads (8 warps, 2m x 4n), 2 CTAs/SM.
// Tile: 64 rows x 256 cols. Output cols interleaved (2j=z_j, 2j+1=t_j)
// -> C-fragment pairs are (z,t) -> register-local gates.
// cp.async double-buffered A staging.
#define SM_B  0
#define SM_A0 65536
#define SM_A1 81920
#define SM_PP 98304
#define SM_ZB 99328
#define SM_HB 99840
#define SM_W2 100352
#define GEMM_SMEM 100864

__global__ void __launch_bounds__(256, 2) k_gemm(
    const float* __restrict__ lzb, const float* __restrict__ lhb,
    const float* __restrict__ w2, const float* __restrict__ b2,
    float* __restrict__ out)
{
    extern __shared__ unsigned char smem[];
    uint32_t sb = smem_u32(smem);
    int tid = threadIdx.x;
    int lane = tid & 31;
    int warp = tid >> 5;
    int wm = warp & 1, wn = warp >> 1;     // 2 m-tiles x 4 n-tiles
    int m_base = wm * 32, n_base = wn * 64;
    int tid4 = lane & 3, grp = lane >> 2;

    float* p_part = (float*)(smem + SM_PP);
    float* szb = (float*)(smem + SM_ZB);
    float* shb = (float*)(smem + SM_HB);
    float* sw  = (float*)(smem + SM_W2);

    // load B image (pre-swizzled) + biases
    for (int i = tid * 16; i < 65536; i += 256 * 16)
        *(uint4*)(smem + i) = *(const uint4*)(g_bimg + i);
    if (tid < 128) { szb[tid] = lzb[tid]; shb[tid] = lhb[tid]; sw[tid] = w2[tid]; }
    float bbias = b2[0];

    // per-thread cp.async chunk indices (4 chunks of 16B per thread; 64 rows)
    uint32_t cp_dst[4];
    const __half* cp_src[4];
#pragma unroll
    for (int it = 0; it < 4; it++) {
        int idx = tid + it * 256;         // 0..1023
        int row = idx >> 4, cc = idx & 15;
        cp_dst[it] = (uint32_t)(row * 256 + ((cc ^ (row & 7)) << 4));
        cp_src[it] = g_af + (size_t)row * DH + cc * 8;
    }

    // ldmatrix lane address components
    int a_row = (lane & 7) | (((lane >> 3) & 1) << 3);
    int a_ks  = lane >> 4;
    int b_nrow = (lane & 7) | ((lane >> 4) << 3);
    int b_ks  = (lane >> 3) & 1;
    int swz = lane & 7;
    uint32_t aRow0 = (uint32_t)(m_base + a_row) * 256;
    uint32_t aRow1 = (uint32_t)(m_base + 16 + a_row) * 256;
    uint32_t bRow[4];
#pragma unroll
    for (int q = 0; q < 4; q++) bRow[q] = (uint32_t)(n_base + q * 16 + b_nrow) * 256;

    // prologue prefetch: first tile into A0
    {
        size_t srcOfs = (size_t)(blockIdx.x << 6) * DH;
        uint32_t base = sb + SM_A0;
#pragma unroll
        for (int it = 0; it < 4; it++)
            CP_ASYNC16(base + cp_dst[it], cp_src[it] + srcOfs);
    }
    CP_COMMIT;
    __syncthreads();   // B image + biases ready

    int buf = 0;
    for (int tile = blockIdx.x; tile < NT64; tile += gridDim.x) {
        int rowBase = tile << 6;
        // prefetch next tile into other buffer
        int nxt = tile + gridDim.x;
        if (nxt < NT64) {
            size_t srcOfs = (size_t)(nxt << 6) * DH;
            uint32_t base = sb + (buf ? SM_A0 : SM_A1);
#pragma unroll
            for (int it = 0; it < 4; it++)
                CP_ASYNC16(base + cp_dst[it], cp_src[it] + srcOfs);
        }
        CP_COMMIT;
        CP_WAIT1;          // current tile's group complete
        __syncthreads();

        uint32_t aS = sb + (buf ? SM_A1 : SM_A0);
        uint32_t bS = sb + SM_B;

        float c[2][8][4];
#pragma unroll
        for (int mt = 0; mt < 2; mt++)
#pragma unroll
            for (int nt = 0; nt < 8; nt++)
#pragma unroll
                for (int q = 0; q < 4; q++) c[mt][nt][q] = 0.f;

#pragma unroll
        for (int kt = 0; kt < 8; kt++) {
            int kc = kt * 2;
            uint32_t a0[4], a1[4], bfr[4][4];
            uint32_t aoff = (uint32_t)(((kc + a_ks) ^ swz) << 4);
            LDSM4(a0, aS + aRow0 + aoff);
            LDSM4(a1, aS + aRow1 + aoff);
            uint32_t boff = (uint32_t)(((kc + b_ks) ^ swz) << 4);
#pragma unroll
            for (int q = 0; q < 4; q++) LDSM4(bfr[q], bS + bRow[q] + boff);
#pragma unroll
            for (int nt = 0; nt < 8; nt++) {
                uint32_t b0v = bfr[nt >> 1][(nt & 1) * 2];
                uint32_t b1v = bfr[nt >> 1][(nt & 1) * 2 + 1];
                MMA16816(c[0][nt], a0, b0v, b1v);
                MMA16816(c[1][nt], a1, b0v, b1v);
            }
        }

        // gate epilogue (single-div form):
        // (1-sigmoid(z)) * tanh(t) = (e^{2t} - 1) / ((1 + e^{z}) (e^{2t} + 1))
        float pr[4] = {0.f, 0.f, 0.f, 0.f};
#pragma unroll
        for (int nt = 0; nt < 8; nt++) {
            int jj = (n_base >> 1) + nt * 4 + tid4;
            float zb = szb[jj], hb = shb[jj], w = sw[jj];
#pragma unroll
            for (int mt = 0; mt < 2; mt++) {
                {
                    float eu = __expf(c[mt][nt][0] + zb);
                    float e2 = __expf(2.f * (c[mt][nt][1] + hb));
                    float term = __fdividef(e2 - 1.f, (1.f + eu) * (e2 + 1.f));
                    pr[mt * 2 + 0] += term * w;
                }
                {
                    float eu = __expf(c[mt][nt][2] + zb);
                    float e2 = __expf(2.f * (c[mt][nt][3] + hb));
                    float term = __fdividef(e2 - 1.f, (1.f + eu) * (e2 + 1.f));
                    pr[mt * 2 + 1] += term * w;
                }
            }
        }
#pragma unroll
        for (int q = 0; q < 4; q++) {
            pr[q] += __shfl_xor_sync(0xffffffffu, pr[q], 1);
            pr[q] += __shfl_xor_sync(0xffffffffu, pr[q], 2);
        }
        if (tid4 == 0) {
            p_part[wn * 64 + m_base + grp]          = pr[0];
            p_part[wn * 64 + m_base + grp + 8]      = pr[1];
            p_part[wn * 64 + m_base + 16 + grp]     = pr[2];
            p_part[wn * 64 + m_base + 16 + grp + 8] = pr[3];
        }
        __syncthreads();
        if (tid < 64) {
            int row = rowBase + tid;
            if (row < NN)
                out[row] = p_part[tid] + p_part[64 + tid] +
                           p_part[128 + tid] + p_part[192 + tid] + bbias;
        }
        __syncthreads();
        buf ^= 1;
    }
}

// ---------------- launcher ----------------
// metadata order: x, edge_index, Wz, bz, Wr, br, Wh, bh,
//                 lzW, lzb, lrW, lrb, lhW, lhb, W2, b2
// Graph-level concurrency (proven R11 pattern):
//   s2: wp (immediately — depends only on weights), dinvxs (after deg)
//   s0: init, deg, scan1-3, fill, then join, gather, gemm
extern "C" void kernel_launch(void* const* d_in, const int* in_sizes, int n_in,
                              void* d_out, int out_size) {
    const float4* x4  = (const float4*)d_in[0];
    const void*   ei  = d_in[1];
    const float*  Wz  = (const float*)d_in[2];
    const float*  Wh  = (const float*)d_in[6];
    const float*  lzW = (const float*)d_in[8];
    const float*  lzb = (const float*)d_in[9];
    const float*  lhW = (const float*)d_in[12];
    const float*  lhb = (const float*)d_in[13];
    const float*  W2  = (const float*)d_in[14];
    const float*  b2  = (const float*)d_in[15];
    float* out = (float*)d_out;

    cudaFuncSetAttribute(k_gemm, cudaFuncAttributeMaxDynamicSharedMemorySize, GEMM_SMEM);

    cudaStream_t s2 = 0;
    cudaEvent_t evStart = 0, evDeg = 0, evB = 0;
    bool forked = false;
    if (cudaStreamCreateWithFlags(&s2, cudaStreamNonBlocking) == cudaSuccess &&
        cudaEventCreateWithFlags(&evStart, cudaEventDisableTiming) == cudaSuccess &&
        cudaEventCreateWithFlags(&evDeg, cudaEventDisableTiming) == cudaSuccess &&
        cudaEventCreateWithFlags(&evB, cudaEventDisableTiming) == cudaSuccess)
        forked = true;

    if (forked) {
        // wp has no dependency on graph data: start it immediately on s2
        cudaEventRecord(evStart, 0);
        cudaStreamWaitEvent(s2, evStart, 0);
        k_wp<<<dim3(DH, 2), DH, 0, s2>>>(Wz, lzW, Wh, lhW);

        k_init<<<(NN + 255) / 256, 256>>>((const unsigned int*)ei);
        k_deg<<<(NE / 8 + 255) / 256, 256>>>(ei);
        cudaEventRecord(evDeg, 0);
        cudaStreamWaitEvent(s2, evDeg, 0);
        k_dinvxs<<<DX_STRIDE / 256, 256, 0, s2>>>(x4);
        cudaEventRecord(evB, s2);

        k_scan1<<<NB, SCAN_B>>>();
        k_scan2<<<1, 128>>>();
        k_scan3<<<(NN + 256) / 256, 256>>>();
        k_fill<<<(NE / 4 + 255) / 256, 256>>>(ei);

        cudaStreamWaitEvent(0, evB, 0);   // join before gather
    } else {
        k_init<<<(NN + 255) / 256, 256>>>((const unsigned int*)ei);
        k_wp<<<dim3(DH, 2), DH>>>(Wz, lzW, Wh, lhW);
        k_deg<<<(NE / 8 + 255) / 256, 256>>>(ei);
        k_dinvxs<<<DX_STRIDE / 256, 256>>>(x4);
        k_scan1<<<NB, SCAN_B>>>();
        k_scan2<<<1, 128>>>();
        k_scan3<<<(NN + 256) / 256, 256>>>();
        k_fill<<<(NE / 4 + 255) / 256, 256>>>(ei);
    }

    k_gather<<<(NN * 32 + 255) / 256, 256>>>();
    k_gemm<<<296, 256, GEMM_SMEM>>>(lzb, lhb, W2, b2, out);
}

// round 16
// speedup vs baseline: 1.2264x; 1.0289x over previous
#include <cuda_runtime.h>
#include <cuda_fp16.h>
#include <math.h>
#include <stdint.h>

#define NN 100000
#define NE 1600000
#define DH 128
#define NPAD 100096                  // padded rows (multiple of 128)
#define NT64 1564                    // NPAD / 64 tiles
#define SCAN_B 1024
#define NB ((NN + SCAN_B - 1) / SCAN_B)

// ---------------- device scratch (no allocations allowed) ----------------
__device__ int     g_is64;
__device__ int     g_tile;                            // gemm work-steal counter
__device__ int     g_deg[NN];
__device__ int     g_cur[NN];
__device__ int     g_scan[NB * SCAN_B];
__device__ int     g_bsum[NB];
__device__ int     g_boff[NB];
__device__ int     g_off[NN + 1];
__device__ int     g_csr[NE];                         // src ids grouped by dst
__device__ float   g_dinv[NN];
__device__ __half2 g_xsh[(size_t)NN * 64];            // dinv-scaled x fp16, 25.6MB
__device__ __align__(16) __half g_af[(size_t)NPAD * DH];   // agg fp16 (pad rows 0)
__device__ __align__(16) unsigned char g_bimg[65536];      // B fp16, [n][k] swizzled

// ---------------- helpers ----------------
__device__ __forceinline__ uint32_t smem_u32(const void* p) {
    uint32_t a;
    asm("{ .reg .u64 t; cvta.to.shared.u64 t, %1; cvt.u32.u64 %0, t; }" : "=r"(a) : "l"(p));
    return a;
}

#define LDSM4(r, addr) \
    asm volatile("ldmatrix.sync.aligned.m8n8.x4.shared.b16 {%0,%1,%2,%3}, [%4];" \
        : "=r"((r)[0]), "=r"((r)[1]), "=r"((r)[2]), "=r"((r)[3]) : "r"(addr))

#define MMA16816(c, a, b0v, b1v) \
    asm volatile("mma.sync.aligned.m16n8k16.row.col.f32.f16.f16.f32 " \
        "{%0,%1,%2,%3}, {%4,%5,%6,%7}, {%8,%9}, {%0,%1,%2,%3};" \
        : "+f"((c)[0]), "+f"((c)[1]), "+f"((c)[2]), "+f"((c)[3]) \
        : "r"((a)[0]), "r"((a)[1]), "r"((a)[2]), "r"((a)[3]), "r"(b0v), "r"(b1v))

#define CP_ASYNC16(dst, src) \
    asm volatile("cp.async.cg.shared.global [%0], [%1], 16;" :: "r"(dst), "l"(src))
#define CP_COMMIT  asm volatile("cp.async.commit_group;" ::: "memory")
#define CP_WAIT1   asm volatile("cp.async.wait_group 1;" ::: "memory")

// ------- init counters + dtype detection (fused) --------------------------
__global__ void k_init(const unsigned int* __restrict__ e) {
    int i = blockIdx.x * blockDim.x + threadIdx.x;
    if (i < NN) { g_deg[i] = 0; g_cur[i] = 0; }
    if (i == 0) {
        g_tile = 0;
        int ok = 1;
#pragma unroll
        for (int q = 0; q < 64; q++) ok &= (e[2 * q + 1] == 0u);
        g_is64 = ok;   // all high words zero -> int64
    }
}

// ------- fold weights -> fp16 B image, z/t column-interleaved ------------
__global__ void k_wp(const float* __restrict__ Wz, const float* __restrict__ lzW,
                     const float* __restrict__ Wh, const float* __restrict__ lhW) {
    int k = blockIdx.x;        // 0..127 (GEMM K dim)
    int half = blockIdx.y;     // 0: z, 1: t
    int j = threadIdx.x;       // 0..127
    const float* W = half ? Wh : Wz;
    const float* L = half ? lhW : lzW;
    float acc = 0.f;
#pragma unroll 4
    for (int c = 0; c < DH; c++) acc += W[k * DH + c] * L[c * DH + j];
    int n = 2 * j + half;
    int off = n * 256 + (((k >> 3) ^ (n & 7)) << 4) + (k & 7) * 2;
    *(__half*)(g_bimg + off) = __float2half_rn(acc);
}

// ---------------- degree (dst only), 4 edges per thread -------------------
__global__ void k_deg(const void* __restrict__ e) {
    int t = blockIdx.x * blockDim.x + threadIdx.x;
    if (t >= NE / 4) return;
    int d0, d1, d2, d3;
    if (g_is64) {
        const ulonglong2* p = (const ulonglong2*)((const long long*)e + NE);
        ulonglong2 a = p[2 * t], b = p[2 * t + 1];
        d0 = (int)a.x; d1 = (int)a.y; d2 = (int)b.x; d3 = (int)b.y;
    } else {
        const int4* p = (const int4*)((const int*)e + NE);
        int4 a = p[t];
        d0 = a.x; d1 = a.y; d2 = a.z; d3 = a.w;
    }
    atomicAdd(&g_deg[d0], 1);
    atomicAdd(&g_deg[d1], 1);
    atomicAdd(&g_deg[d2], 1);
    atomicAdd(&g_deg[d3], 1);
}

// ------- fused dinv + xs: thread per 16B chunk, 4 independent iters -------
#define DX_STRIDE 800000
__global__ void __launch_bounds__(256) k_dinvxs(const float4* __restrict__ x4) {
    int base = blockIdx.x * blockDim.x + threadIdx.x;
#pragma unroll
    for (int k = 0; k < 4; k++) {
        int idx = base + k * DX_STRIDE;
        int node = idx >> 5;
        float di = rsqrtf((float)g_deg[node] + 2.0f);
        float4 v = __ldcs(&x4[idx]);
        __half2 h0 = __floats2half2_rn(v.x * di, v.y * di);
        __half2 h1 = __floats2half2_rn(v.z * di, v.w * di);
        uint2 o;
        o.x = *reinterpret_cast<uint32_t*>(&h0);
        o.y = *reinterpret_cast<uint32_t*>(&h1);
        *(uint2*)&g_xsh[(size_t)idx * 2] = o;
        if ((idx & 31) == 0) g_dinv[node] = di;
    }
}

// ---------------- prefix scan of degrees (3 phases) ----------------
__global__ void k_scan1() {
    __shared__ int sbuf[SCAN_B];
    int tid = threadIdx.x;
    int i = blockIdx.x * SCAN_B + tid;
    int v = (i < NN) ? g_deg[i] : 0;
    sbuf[tid] = v;
    __syncthreads();
#pragma unroll
    for (int ofs = 1; ofs < SCAN_B; ofs <<= 1) {
        int t = (tid >= ofs) ? sbuf[tid - ofs] : 0;
        __syncthreads();
        sbuf[tid] += t;
        __syncthreads();
    }
    g_scan[blockIdx.x * SCAN_B + tid] = sbuf[tid];
    if (tid == SCAN_B - 1) g_bsum[blockIdx.x] = sbuf[tid];
}

__global__ void k_scan2() {
    __shared__ int sb[128];
    int t = threadIdx.x;
    int v = (t < NB) ? g_bsum[t] : 0;
    sb[t] = v;
    __syncthreads();
#pragma unroll
    for (int o = 1; o < 128; o <<= 1) {
        int u = (t >= o) ? sb[t - o] : 0;
        __syncthreads();
        sb[t] += u;
        __syncthreads();
    }
    if (t < NB) g_boff[t] = sb[t] - v;   // exclusive prefix
}

__global__ void k_scan3() {
    int i = blockIdx.x * blockDim.x + threadIdx.x;
    if (i < NN) g_off[i] = g_scan[i] - g_deg[i] + g_boff[i >> 10];
    if (i == NN) g_off[NN] = NE;
}

// ---------------- fill CSR, 4 edges per thread ----------------
__global__ void k_fill(const void* __restrict__ e) {
    int t = blockIdx.x * blockDim.x + threadIdx.x;
    if (t >= NE / 4) return;
    int s0, s1, s2, s3, d0, d1, d2, d3;
    if (g_is64) {
        const ulonglong2* ps = (const ulonglong2*)e;
        const ulonglong2* pd = (const ulonglong2*)((const long long*)e + NE);
        ulonglong2 a0 = ps[2 * t], a1 = ps[2 * t + 1];
        ulonglong2 b0 = pd[2 * t], b1 = pd[2 * t + 1];
        s0 = (int)a0.x; s1 = (int)a0.y; s2 = (int)a1.x; s3 = (int)a1.y;
        d0 = (int)b0.x; d1 = (int)b0.y; d2 = (int)b1.x; d3 = (int)b1.y;
    } else {
        const int4* ps = (const int4*)e;
        const int4* pd = (const int4*)((const int*)e + NE);
        int4 a = ps[t], b = pd[t];
        s0 = a.x; s1 = a.y; s2 = a.z; s3 = a.w;
        d0 = b.x; d1 = b.y; d2 = b.z; d3 = b.w;
    }
    int p0 = atomicAdd(&g_cur[d0], 1); g_csr[g_off[d0] + p0] = s0;
    int p1 = atomicAdd(&g_cur[d1], 1); g_csr[g_off[d1] + p1] = s1;
    int p2 = atomicAdd(&g_cur[d2], 1); g_csr[g_off[d2] + p2] = s2;
    int p3 = atomicAdd(&g_cur[d3], 1); g_csr[g_off[d3] + p3] = s3;
}

// ---------------- gather -> fp16 A ----------------
__device__ __forceinline__ void acc_h2pair(float4& a, uint2 raw) {
    float2 f0 = __half22float2(*reinterpret_cast<const __half2*>(&raw.x));
    float2 f1 = __half22float2(*reinterpret_cast<const __half2*>(&raw.y));
    a.x += f0.x; a.y += f0.y; a.z += f1.x; a.w += f1.y;
}

__global__ void __launch_bounds__(256) k_gather() {
    int n = (blockIdx.x * blockDim.x + threadIdx.x) >> 5;
    int lane = threadIdx.x & 31;
    if (n >= NN) return;
    int j = g_off[n];
    int jend = g_off[n + 1];
    const uint2* xs = (const uint2*)g_xsh;
    float4 a0 = make_float4(0.f, 0.f, 0.f, 0.f);
    float4 a1 = make_float4(0.f, 0.f, 0.f, 0.f);
    {
        uint2 raw = xs[(long long)n * 32 + lane];
        acc_h2pair(a0, raw);
        a0.x *= 2.f; a0.y *= 2.f; a0.z *= 2.f; a0.w *= 2.f;
    }
    // 8-wide main loop: deeper MLP per warp
    for (; j + 8 <= jend; j += 8) {
        int s[8];
#pragma unroll
        for (int q = 0; q < 8; q++) s[q] = __ldcs(&g_csr[j + q]);
        uint2 rr[8];
#pragma unroll
        for (int q = 0; q < 8; q++) rr[q] = xs[(long long)s[q] * 32 + lane];
#pragma unroll
        for (int q = 0; q < 8; q += 2) {
            acc_h2pair(a0, rr[q]);
            acc_h2pair(a1, rr[q + 1]);
        }
    }
    for (; j + 2 <= jend; j += 2) {
        int s0 = __ldcs(&g_csr[j]);
        int s1 = __ldcs(&g_csr[j + 1]);
        uint2 r0 = xs[(long long)s0 * 32 + lane];
        uint2 r1 = xs[(long long)s1 * 32 + lane];
        acc_h2pair(a0, r0);
        acc_h2pair(a1, r1);
    }
    if (j < jend) {
        int s = __ldcs(&g_csr[j]);
        uint2 r = xs[(long long)s * 32 + lane];
        acc_h2pair(a1, r);
    }
    float di = g_dinv[n];
    uint2 H;
    __half2 h0 = __floats2half2_rn(di * (a0.x + a1.x), di * (a0.y + a1.y));
    __half2 h1 = __floats2half2_rn(di * (a0.z + a1.z), di * (a0.w + a1.w));
    H.x = *reinterpret_cast<uint32_t*>(&h0);
    H.y = *reinterpret_cast<uint32_t*>(&h1);
    *(uint2*)&g_af[(size_t)n * DH + lane * 4] = H;
}

// ---------------- HMMA GEMM (mma.sync fp16) + gate epilogue -------------
// persistent, 256 threads (8 warps, 2m x 4n), 2 CTAs/SM, DYNAMIC work
// stealing via global tile counter (perfect balance, no quantized tail).
// Tile: 64 rows x 256 cols. Output cols interleaved (2j=z_j, 2j+1=t_j).
#define SM_B    0
#define SM_A0   65536
#define SM_A1   81920
#define SM_PP   98304
#define SM_ZB   99328
#define SM_HB   99840
#define SM_W2   100352
#define SM_NXT  100864
#define GEMM_SMEM 100880

__global__ void __launch_bounds__(256, 2) k_gemm(
    const float* __restrict__ lzb, const float* __restrict__ lhb,
    const float* __restrict__ w2, const float* __restrict__ b2,
    float* __restrict__ out)
{
    extern __shared__ unsigned char smem[];
    uint32_t sb = smem_u32(smem);
    int tid = threadIdx.x;
    int lane = tid & 31;
    int warp = tid >> 5;
    int wm = warp & 1, wn = warp >> 1;     // 2 m-tiles x 4 n-tiles
    int m_base = wm * 32, n_base = wn * 64;
    int tid4 = lane & 3, grp = lane >> 2;

    float* p_part = (float*)(smem + SM_PP);
    float* szb = (float*)(smem + SM_ZB);
    float* shb = (float*)(smem + SM_HB);
    float* sw  = (float*)(smem + SM_W2);
    int* s_nxt = (int*)(smem + SM_NXT);

    // load B image (pre-swizzled) + biases
    for (int i = tid * 16; i < 65536; i += 256 * 16)
        *(uint4*)(smem + i) = *(const uint4*)(g_bimg + i);
    if (tid < 128) { szb[tid] = lzb[tid]; shb[tid] = lhb[tid]; sw[tid] = w2[tid]; }
    float bbias = b2[0];

    // per-thread cp.async chunk indices (4 chunks of 16B per thread; 64 rows)
    uint32_t cp_dst[4];
    const __half* cp_src[4];
#pragma unroll
    for (int it = 0; it < 4; it++) {
        int idx = tid + it * 256;         // 0..1023
        int row = idx >> 4, cc = idx & 15;
        cp_dst[it] = (uint32_t)(row * 256 + ((cc ^ (row & 7)) << 4));
        cp_src[it] = g_af + (size_t)row * DH + cc * 8;
    }

    // ldmatrix lane address components
    int a_row = (lane & 7) | (((lane >> 3) & 1) << 3);
    int a_ks  = lane >> 4;
    int b_nrow = (lane & 7) | ((lane >> 4) << 3);
    int b_ks  = (lane >> 3) & 1;
    int swz = lane & 7;
    uint32_t aRow0 = (uint32_t)(m_base + a_row) * 256;
    uint32_t aRow1 = (uint32_t)(m_base + 16 + a_row) * 256;
    uint32_t bRow[4];
#pragma unroll
    for (int q = 0; q < 4; q++) bRow[q] = (uint32_t)(n_base + q * 16 + b_nrow) * 256;

    // grab first tile + prefetch into A0
    if (tid == 0) s_nxt[0] = atomicAdd(&g_tile, 1);
    __syncthreads();            // B image + biases + s_nxt ready
    int cur = s_nxt[0];
    if (cur < NT64) {
        size_t srcOfs = (size_t)(cur << 6) * DH;
        uint32_t base = sb + SM_A0;
#pragma unroll
        for (int it = 0; it < 4; it++)
            CP_ASYNC16(base + cp_dst[it], cp_src[it] + srcOfs);
    }
    CP_COMMIT;

    int buf = 0;
    while (cur < NT64) {
        int rowBase = cur << 6;
        // steal next tile, broadcast, prefetch into other buffer
        if (tid == 0) s_nxt[0] = atomicAdd(&g_tile, 1);
        __syncthreads();
        int nxt = s_nxt[0];
        if (nxt < NT64) {
            size_t srcOfs = (size_t)(nxt << 6) * DH;
            uint32_t base = sb + (buf ? SM_A0 : SM_A1);
#pragma unroll
            for (int it = 0; it < 4; it++)
                CP_ASYNC16(base + cp_dst[it], cp_src[it] + srcOfs);
        }
        CP_COMMIT;
        CP_WAIT1;          // current tile's group complete
        __syncthreads();

        uint32_t aS = sb + (buf ? SM_A1 : SM_A0);
        uint32_t bS = sb + SM_B;

        float c[2][8][4];
#pragma unroll
        for (int mt = 0; mt < 2; mt++)
#pragma unroll
            for (int nt = 0; nt < 8; nt++)
#pragma unroll
                for (int q = 0; q < 4; q++) c[mt][nt][q] = 0.f;

#pragma unroll
        for (int kt = 0; kt < 8; kt++) {
            int kc = kt * 2;
            uint32_t a0[4], a1[4], bfr[4][4];
            uint32_t aoff = (uint32_t)(((kc + a_ks) ^ swz) << 4);
            LDSM4(a0, aS + aRow0 + aoff);
            LDSM4(a1, aS + aRow1 + aoff);
            uint32_t boff = (uint32_t)(((kc + b_ks) ^ swz) << 4);
#pragma unroll
            for (int q = 0; q < 4; q++) LDSM4(bfr[q], bS + bRow[q] + boff);
#pragma unroll
            for (int nt = 0; nt < 8; nt++) {
                uint32_t b0v = bfr[nt >> 1][(nt & 1) * 2];
                uint32_t b1v = bfr[nt >> 1][(nt & 1) * 2 + 1];
                MMA16816(c[0][nt], a0, b0v, b1v);
                MMA16816(c[1][nt], a1, b0v, b1v);
            }
        }

        // gate epilogue (single-div form):
        // (1-sigmoid(z)) * tanh(t) = (e^{2t} - 1) / ((1 + e^{z}) (e^{2t} + 1))
        float pr[4] = {0.f, 0.f, 0.f, 0.f};
#pragma unroll
        for (int nt = 0; nt < 8; nt++) {
            int jj = (n_base >> 1) + nt * 4 + tid4;
            float zb = szb[jj], hb = shb[jj], w = sw[jj];
#pragma unroll
            for (int mt = 0; mt < 2; mt++) {
                {
                    float eu = __expf(c[mt][nt][0] + zb);
                    float e2 = __expf(2.f * (c[mt][nt][1] + hb));
                    float term = __fdividef(e2 - 1.f, (1.f + eu) * (e2 + 1.f));
                    pr[mt * 2 + 0] += term * w;
                }
                {
                    float eu = __expf(c[mt][nt][2] + zb);
                    float e2 = __expf(2.f * (c[mt][nt][3] + hb));
                    float term = __fdividef(e2 - 1.f, (1.f + eu) * (e2 + 1.f));
                    pr[mt * 2 + 1] += term * w;
                }
            }
        }
#pragma unroll
        for (int q = 0; q < 4; q++) {
            pr[q] += __shfl_xor_sync(0xffffffffu, pr[q], 1);
            pr[q] += __shfl_xor_sync(0xffffffffu, pr[q], 2);
        }
        if (tid4 == 0) {
            p_part[wn * 64 + m_base + grp]          = pr[0];
            p_part[wn * 64 + m_base + grp + 8]      = pr[1];
            p_part[wn * 64 + m_base + 16 + grp]     = pr[2];
            p_part[wn * 64 + m_base + 16 + grp + 8] = pr[3];
        }
        __syncthreads();
        if (tid < 64) {
            int row = rowBase + tid;
            if (row < NN)
                out[row] = p_part[tid] + p_part[64 + tid] +
                           p_part[128 + tid] + p_part[192 + tid] + bbias;
        }
        __syncthreads();   // protects p_part and s_nxt before next iteration
        cur = nxt;
        buf ^= 1;
    }
}

// ---------------- launcher ----------------
// metadata order: x, edge_index, Wz, bz, Wr, br, Wh, bh,
//                 lzW, lzb, lrW, lrb, lhW, lhb, W2, b2
// Graph-level concurrency (proven R11 pattern):
//   s2: wp (immediately — depends only on weights), dinvxs (after deg)
//   s0: init, deg, scan1-3, fill, then join, gather, gemm
extern "C" void kernel_launch(void* const* d_in, const int* in_sizes, int n_in,
                              void* d_out, int out_size) {
    const float4* x4  = (const float4*)d_in[0];
    const void*   ei  = d_in[1];
    const float*  Wz  = (const float*)d_in[2];
    const float*  Wh  = (const float*)d_in[6];
    const float*  lzW = (const float*)d_in[8];
    const float*  lzb = (const float*)d_in[9];
    const float*  lhW = (const float*)d_in[12];
    const float*  lhb = (const float*)d_in[13];
    const float*  W2  = (const float*)d_in[14];
    const float*  b2  = (const float*)d_in[15];
    float* out = (float*)d_out;

    cudaFuncSetAttribute(k_gemm, cudaFuncAttributeMaxDynamicSharedMemorySize, GEMM_SMEM);

    cudaStream_t s2 = 0;
    cudaEvent_t evStart = 0, evDeg = 0, evB = 0;
    bool forked = false;
    if (cudaStreamCreateWithFlags(&s2, cudaStreamNonBlocking) == cudaSuccess &&
        cudaEventCreateWithFlags(&evStart, cudaEventDisableTiming) == cudaSuccess &&
        cudaEventCreateWithFlags(&evDeg, cudaEventDisableTiming) == cudaSuccess &&
        cudaEventCreateWithFlags(&evB, cudaEventDisableTiming) == cudaSuccess)
        forked = true;

    if (forked) {
        // wp has no dependency on graph data: start it immediately on s2
        cudaEventRecord(evStart, 0);
        cudaStreamWaitEvent(s2, evStart, 0);
        k_wp<<<dim3(DH, 2), DH, 0, s2>>>(Wz, lzW, Wh, lhW);

        k_init<<<(NN + 255) / 256, 256>>>((const unsigned int*)ei);
        k_deg<<<(NE / 4 + 255) / 256, 256>>>(ei);
        cudaEventRecord(evDeg, 0);
        cudaStreamWaitEvent(s2, evDeg, 0);
        k_dinvxs<<<DX_STRIDE / 256, 256, 0, s2>>>(x4);
        cudaEventRecord(evB, s2);

        k_scan1<<<NB, SCAN_B>>>();
        k_scan2<<<1, 128>>>();
        k_scan3<<<(NN + 256) / 256, 256>>>();
        k_fill<<<(NE / 4 + 255) / 256, 256>>>(ei);

        cudaStreamWaitEvent(0, evB, 0);   // join before gather
    } else {
        k_init<<<(NN + 255) / 256, 256>>>((const unsigned int*)ei);
        k_wp<<<dim3(DH, 2), DH>>>(Wz, lzW, Wh, lhW);
        k_deg<<<(NE / 4 + 255) / 256, 256>>>(ei);
        k_dinvxs<<<DX_STRIDE / 256, 256>>>(x4);
        k_scan1<<<NB, SCAN_B>>>();
        k_scan2<<<1, 128>>>();
        k_scan3<<<(NN + 256) / 256, 256>>>();
        k_fill<<<(NE / 4 + 255) / 256, 256>>>(ei);
    }

    k_gather<<<(NN * 32 + 255) / 256, 256>>>();
    k_gemm<<<296, 256, GEMM_SMEM>>>(lzb, lhb, W2, b2, out);
}